// round 7
// baseline (speedup 1.0000x reference)
#include <cuda_runtime.h>
#include <cstdint>

// M=512 memories, T=512, D=128, E=512, NTAGS=74, GH=64, LH=256

__device__ __align__(16) float d_dots[512];
__device__ __align__(16) float d_p[512];
__device__ __align__(16) float d_wmem[512 * 128];
__device__ __align__(16) float d_gigru0[512 * 192];
__device__ __align__(16) float d_gigru1[512 * 192];
__device__ __align__(16) float d_hgru[512 * 128];
__device__ __align__(16) float d_s[512 * 128];
__device__ __align__(16) float d_x[512 * 512];
__device__ __align__(16) float d_gil0[512 * 1024];
__device__ __align__(16) float d_gil1[512 * 1024];
__device__ __align__(16) float d_hlstm[512 * 512];

__device__ __forceinline__ float sigf(float x) {
    return __fdividef(1.f, 1.f + __expf(-x));
}

// K1: dots[m] = <memory[m], u>
__global__ __launch_bounds__(256) void k_dots(const float* __restrict__ memory,
                                              const float* __restrict__ u) {
    const int tid = threadIdx.x;
    const float4* m4 = (const float4*)memory + (size_t)blockIdx.x * 16384;
    const float4* u4 = (const float4*)u;
    float acc = 0.f;
#pragma unroll 4
    for (int i = tid; i < 16384; i += 256) {
        float4 a = m4[i];
        float4 b = u4[i];
        acc += a.x * b.x + a.y * b.y + a.z * b.z + a.w * b.w;
    }
#pragma unroll
    for (int o = 16; o; o >>= 1) acc += __shfl_xor_sync(0xffffffffu, acc, o);
    __shared__ float sred[8];
    if ((tid & 31) == 0) sred[tid >> 5] = acc;
    __syncthreads();
    if (tid == 0) {
        float s = 0.f;
#pragma unroll
        for (int i = 0; i < 8; i++) s += sred[i];
        d_dots[blockIdx.x] = s;
    }
}

// K2: p = softmax(dots)
__global__ void k_softp() {
    const int tid = threadIdx.x;
    float v = d_dots[tid];
    __shared__ float s1[16];
    __shared__ float stot;
    float m = v;
#pragma unroll
    for (int o = 16; o; o >>= 1) m = fmaxf(m, __shfl_xor_sync(0xffffffffu, m, o));
    if ((tid & 31) == 0) s1[tid >> 5] = m;
    __syncthreads();
    if (tid == 0) {
        float mm = s1[0];
#pragma unroll
        for (int i = 1; i < 16; i++) mm = fmaxf(mm, s1[i]);
        stot = mm;
    }
    __syncthreads();
    float e = __expf(v - stot);
    float ssum = e;
#pragma unroll
    for (int o = 16; o; o >>= 1) ssum += __shfl_xor_sync(0xffffffffu, ssum, o);
    if ((tid & 31) == 0) s1[tid >> 5] = ssum;
    __syncthreads();
    if (tid == 0) {
        float ss = 0.f;
#pragma unroll
        for (int i = 0; i < 16; i++) ss += s1[i];
        stot = ss;
    }
    __syncthreads();
    d_p[tid] = e * __fdividef(1.f, stot);
}

// K3: wmem = sum_m p[m]*memory[m]
__global__ __launch_bounds__(128) void k_wmem(const float* __restrict__ memory) {
    __shared__ float ps[512];
    const int tid = threadIdx.x;
    for (int i = tid; i < 512; i += 128) ps[i] = d_p[i];
    __syncthreads();
    const float4* m4 = (const float4*)memory;
    const size_t base = (size_t)blockIdx.x * 128 + tid;
    float4 acc = {0.f, 0.f, 0.f, 0.f};
    for (int m = 0; m < 512; m += 8) {
#pragma unroll
        for (int q = 0; q < 8; q++) {
            float pm = ps[m + q];
            float4 v = m4[(size_t)(m + q) * 16384 + base];
            acc.x = fmaf(pm, v.x, acc.x);
            acc.y = fmaf(pm, v.y, acc.y);
            acc.z = fmaf(pm, v.z, acc.z);
            acc.w = fmaf(pm, v.w, acc.w);
        }
    }
    ((float4*)d_wmem)[base] = acc;
}

// K4: G[t] = [wmem[t]|u[t]]@W_ff.T + b_ff; gi_gru = G@gWih.T + gbih
__global__ __launch_bounds__(192) void k_G_gi(const float* __restrict__ u,
                                              const float* __restrict__ W_ff,
                                              const float* __restrict__ b_ff,
                                              const float* __restrict__ gWih_f,
                                              const float* __restrict__ gbih_f,
                                              const float* __restrict__ gWih_b,
                                              const float* __restrict__ gbih_b) {
    const int t = blockIdx.x;
    const int tid = threadIdx.x;
    __shared__ __align__(16) float c[256];
    __shared__ __align__(16) float gsm[128];
    if (tid < 128) {
        c[tid] = d_wmem[t * 128 + tid];
        c[128 + tid] = u[t * 128 + tid];
    }
    __syncthreads();
    if (tid < 128) {
        const float4* wr = (const float4*)(W_ff + tid * 256);
        const float4* c4 = (const float4*)c;
        float a0 = 0.f, a1 = 0.f;
#pragma unroll 8
        for (int i = 0; i < 64; i += 2) {
            float4 w0 = wr[i], w1 = wr[i + 1];
            float4 x0 = c4[i], x1 = c4[i + 1];
            a0 += w0.x * x0.x + w0.y * x0.y + w0.z * x0.z + w0.w * x0.w;
            a1 += w1.x * x1.x + w1.y * x1.y + w1.z * x1.z + w1.w * x1.w;
        }
        gsm[tid] = a0 + a1 + b_ff[tid];
    }
    __syncthreads();
    {
        const float4* wf = (const float4*)(gWih_f + tid * 128);
        const float4* wb = (const float4*)(gWih_b + tid * 128);
        const float4* g4 = (const float4*)gsm;
        float af = gbih_f[tid];
        float ab = gbih_b[tid];
#pragma unroll 8
        for (int i = 0; i < 32; i++) {
            float4 gv = g4[i];
            float4 a = wf[i];
            float4 b = wb[i];
            af += a.x * gv.x + a.y * gv.y + a.z * gv.z + a.w * gv.w;
            ab += b.x * gv.x + b.y * gv.y + b.z * gv.z + b.w * gv.w;
        }
        d_gigru0[t * 192 + tid] = af;
        d_gigru1[t * 192 + tid] = ab;
    }
}

// K5: BiGRU, one CTA per direction. Whh rows in regs (2 threads/row).
__global__ __launch_bounds__(384) void k_gru(const float* __restrict__ Whh_f,
                                             const float* __restrict__ bhh_f,
                                             const float* __restrict__ Whh_b,
                                             const float* __restrict__ bhh_b) {
    const int dir = blockIdx.x;
    const float* Whh = dir ? Whh_b : Whh_f;
    const float* bhh = dir ? bhh_b : bhh_f;
    const float* gi = dir ? d_gigru1 : d_gigru0;
    const int tid = threadIdx.x;
    const int r = tid >> 1;
    const int half = tid & 1;
    float4 w4[8];
    const float4* wsrc = (const float4*)(Whh + r * 64 + half * 32);
#pragma unroll
    for (int i = 0; i < 8; i++) w4[i] = wsrc[i];
    const float brow = bhh[r];
    __shared__ __align__(16) float hb[64];
    __shared__ float garr[192];
    __shared__ float gism[192];
    if (tid < 64) hb[tid] = 0.f;
    float hreg = 0.f;
    __syncthreads();
    for (int s = 0; s < 512; s++) {
        const int t = dir ? 511 - s : s;
        float gval = 0.f;
        if (!half) gval = gi[t * 192 + r];
        const float4* h4 = (const float4*)(hb + half * 32);
        float a0 = 0.f, a1 = 0.f, a2 = 0.f, a3 = 0.f;
#pragma unroll
        for (int i = 0; i < 8; i++) {
            float4 hv = h4[i];
            float4 wv = w4[i];
            a0 = fmaf(wv.x, hv.x, a0);
            a1 = fmaf(wv.y, hv.y, a1);
            a2 = fmaf(wv.z, hv.z, a2);
            a3 = fmaf(wv.w, hv.w, a3);
        }
        float acc = (a0 + a1) + (a2 + a3);
        acc += __shfl_xor_sync(0xffffffffu, acc, 1);
        if (!half) {
            garr[r] = acc + brow;
            gism[r] = gval;
        }
        __syncthreads();
        if (tid < 64) {
            float rr = sigf(gism[tid] + garr[tid]);
            float zz = sigf(gism[64 + tid] + garr[64 + tid]);
            float nn = tanhf(gism[128 + tid] + rr * garr[128 + tid]);
            hreg = (1.f - zz) * nn + zz * hreg;
            d_hgru[t * 128 + dir * 64 + tid] = hreg;
            hb[tid] = hreg;
        }
        __syncthreads();
    }
}

// K6: s = u + h_gru
__global__ void k_uplus(const float* __restrict__ u) {
    int i = blockIdx.x * blockDim.x + threadIdx.x;
    d_s[i] = u[i] + d_hgru[i];
}

// K7: generic NT GEMM C = A@B.T (+bias1+bias2+addm), M=512, 64x64 tiles
__global__ __launch_bounds__(256) void k_gemm_nt(int mode, const float* __restrict__ B,
                                                 int N, int K,
                                                 const float* __restrict__ bias1,
                                                 const float* __restrict__ bias2,
                                                 const float* __restrict__ addm) {
    const float* A = (mode == 0) ? d_s : d_x;
    float* C = (mode == 0) ? d_x : (mode == 1 ? d_gil0 : d_gil1);
    __shared__ __align__(16) float As[16][64];
    __shared__ __align__(16) float Bs[16][64];
    const int tid = threadIdx.x;
    const int tx = tid & 15, ty = tid >> 4;
    const int lrow = tid >> 2, kq = (tid & 3) * 4;
    const float* Ab = A + (size_t)(blockIdx.y * 64 + lrow) * K + kq;
    const float* Bb = B + (size_t)(blockIdx.x * 64 + lrow) * K + kq;
    float acc[4][4] = {};
    for (int k0 = 0; k0 < K; k0 += 16) {
        float4 av = *(const float4*)(Ab + k0);
        float4 bv = *(const float4*)(Bb + k0);
        __syncthreads();
        As[kq][lrow] = av.x;
        As[kq + 1][lrow] = av.y;
        As[kq + 2][lrow] = av.z;
        As[kq + 3][lrow] = av.w;
        Bs[kq][lrow] = bv.x;
        Bs[kq + 1][lrow] = bv.y;
        Bs[kq + 2][lrow] = bv.z;
        Bs[kq + 3][lrow] = bv.w;
        __syncthreads();
#pragma unroll
        for (int kk = 0; kk < 16; kk++) {
            float4 a4 = *(const float4*)(&As[kk][ty * 4]);
            float4 b4 = *(const float4*)(&Bs[kk][tx * 4]);
            float ar[4] = {a4.x, a4.y, a4.z, a4.w};
            float br[4] = {b4.x, b4.y, b4.z, b4.w};
#pragma unroll
            for (int i = 0; i < 4; i++)
#pragma unroll
                for (int j = 0; j < 4; j++)
                    acc[i][j] = fmaf(ar[i], br[j], acc[i][j]);
        }
    }
#pragma unroll
    for (int i = 0; i < 4; i++) {
        int m = blockIdx.y * 64 + ty * 4 + i;
#pragma unroll
        for (int j = 0; j < 4; j++) {
            int n = blockIdx.x * 64 + tx * 4 + j;
            float v = acc[i][j];
            if (bias1) v += bias1[n];
            if (bias2) v += bias2[n];
            if (addm) v += addm[(size_t)m * N + n];
            C[(size_t)m * N + n] = v;
        }
    }
}

// K8: BiLSTM, cluster of 8 CTAs per direction. Whh register-resident.
__global__ __cluster_dims__(8, 1, 1) __launch_bounds__(512, 1)
void k_lstm(const float* __restrict__ Whh_f, const float* __restrict__ Whh_b) {
    const int dir = blockIdx.x >> 3;
    const int rank = blockIdx.x & 7;
    const float* Whh = dir ? Whh_b : Whh_f;
    const float* gi = dir ? d_gil1 : d_gil0;
    const int tid = threadIdx.x;
    const int lrow = tid >> 2;   // 0..127 local gate row
    const int q = tid & 3;       // quarter of the 256-dot
    const int gate = lrow >> 5;
    const int unit = lrow & 31;
    const int grow = gate * 256 + rank * 32 + unit;
    float4 w4[16];
    const float4* wsrc = (const float4*)(Whh + grow * 256 + q * 64);
#pragma unroll
    for (int i = 0; i < 16; i++) w4[i] = wsrc[i];
    __shared__ __align__(16) float hbuf[2][256];
    __shared__ float garr[128];
    if (tid < 256) hbuf[0][tid] = 0.f;
    float cst = 0.f;
    asm volatile("barrier.cluster.arrive.aligned;\n\tbarrier.cluster.wait.aligned;" ::: "memory");
    for (int s = 0; s < 512; s++) {
        const int t = dir ? 511 - s : s;
        float gval = (q == 0) ? gi[t * 1024 + grow] : 0.f;  // incl. bih+bhh
        const float4* h4 = (const float4*)(&hbuf[s & 1][q * 64]);
        float a0 = 0.f, a1 = 0.f, a2 = 0.f, a3 = 0.f;
#pragma unroll
        for (int i = 0; i < 16; i++) {
            float4 hv = h4[i];
            float4 wv = w4[i];
            a0 = fmaf(wv.x, hv.x, a0);
            a1 = fmaf(wv.y, hv.y, a1);
            a2 = fmaf(wv.z, hv.z, a2);
            a3 = fmaf(wv.w, hv.w, a3);
        }
        float acc = (a0 + a1) + (a2 + a3);
        acc += __shfl_xor_sync(0xffffffffu, acc, 1);
        acc += __shfl_xor_sync(0xffffffffu, acc, 2);
        if (q == 0) garr[lrow] = acc + gval;
        __syncthreads();
        if (tid < 32) {
            float iv = sigf(garr[tid]);
            float fv = sigf(garr[32 + tid]);
            float gv = tanhf(garr[64 + tid]);
            float ov = sigf(garr[96 + tid]);
            cst = fv * cst + iv * gv;
            float hv = ov * tanhf(cst);
            d_hlstm[t * 512 + dir * 256 + rank * 32 + tid] = hv;
            unsigned laddr =
                (unsigned)__cvta_generic_to_shared(&hbuf[(s & 1) ^ 1][rank * 32 + tid]);
#pragma unroll
            for (int rt = 0; rt < 8; rt++) {
                unsigned ra;
                asm volatile("mapa.shared::cluster.u32 %0, %1, %2;"
                             : "=r"(ra)
                             : "r"(laddr), "r"(rt));
                asm volatile("st.shared::cluster.f32 [%0], %1;" ::"r"(ra), "f"(hv)
                             : "memory");
            }
        }
        asm volatile("barrier.cluster.arrive.aligned;\n\tbarrier.cluster.wait.aligned;" ::: "memory");
    }
}

// K9: logits + row softmax -> out [512,74]
__global__ __launch_bounds__(128) void k_out(const float* __restrict__ W_out,
                                             const float* __restrict__ b_out,
                                             float* __restrict__ out) {
    const int t = blockIdx.x;
    const int tid = threadIdx.x;
    __shared__ __align__(16) float cb[512];
    __shared__ float red[128];
    ((float4*)cb)[tid] = ((const float4*)(d_hlstm + (size_t)t * 512))[tid];
    __syncthreads();
    float lg = -1e30f;
    if (tid < 74) {
        const float4* wr = (const float4*)(W_out + tid * 512);
        const float4* c4 = (const float4*)cb;
        float a0 = 0.f, a1 = 0.f, a2 = 0.f, a3 = 0.f;
#pragma unroll 8
        for (int i = 0; i < 128; i += 4) {
            float4 w0 = wr[i], w1 = wr[i + 1], w2 = wr[i + 2], w3 = wr[i + 3];
            float4 x0 = c4[i], x1 = c4[i + 1], x2 = c4[i + 2], x3 = c4[i + 3];
            a0 += w0.x * x0.x + w0.y * x0.y + w0.z * x0.z + w0.w * x0.w;
            a1 += w1.x * x1.x + w1.y * x1.y + w1.z * x1.z + w1.w * x1.w;
            a2 += w2.x * x2.x + w2.y * x2.y + w2.z * x2.z + w2.w * x2.w;
            a3 += w3.x * x3.x + w3.y * x3.y + w3.z * x3.z + w3.w * x3.w;
        }
        lg = (a0 + a1) + (a2 + a3) + b_out[tid];
    }
    red[tid] = lg;
    __syncthreads();
#pragma unroll
    for (int o = 64; o > 0; o >>= 1) {
        if (tid < o) red[tid] = fmaxf(red[tid], red[tid + o]);
        __syncthreads();
    }
    float mx = red[0];
    __syncthreads();
    float e = (tid < 74) ? __expf(lg - mx) : 0.f;
    red[tid] = e;
    __syncthreads();
#pragma unroll
    for (int o = 64; o > 0; o >>= 1) {
        if (tid < o) red[tid] += red[tid + o];
        __syncthreads();
    }
    float inv = __fdividef(1.f, red[0]);
    if (tid < 74) out[t * 74 + tid] = e * inv;
}

extern "C" void kernel_launch(void* const* d_in, const int* in_sizes, int n_in,
                              void* d_out, int out_size) {
    const float* memory = (const float*)d_in[0];
    const float* u = (const float*)d_in[1];
    const float* embed = (const float*)d_in[2];
    const float* W_ff = (const float*)d_in[3];
    const float* b_ff = (const float*)d_in[4];
    const float* gWih_f = (const float*)d_in[5];
    const float* gWhh_f = (const float*)d_in[6];
    const float* gbih_f = (const float*)d_in[7];
    const float* gbhh_f = (const float*)d_in[8];
    const float* gWih_b = (const float*)d_in[9];
    const float* gWhh_b = (const float*)d_in[10];
    const float* gbih_b = (const float*)d_in[11];
    const float* gbhh_b = (const float*)d_in[12];
    const float* W_k = (const float*)d_in[13];
    const float* b_k = (const float*)d_in[14];
    const float* lWih_f = (const float*)d_in[15];
    const float* lWhh_f = (const float*)d_in[16];
    const float* lbih_f = (const float*)d_in[17];
    const float* lbhh_f = (const float*)d_in[18];
    const float* lWih_b = (const float*)d_in[19];
    const float* lWhh_b = (const float*)d_in[20];
    const float* lbih_b = (const float*)d_in[21];
    const float* lbhh_b = (const float*)d_in[22];
    const float* W_out = (const float*)d_in[23];
    const float* b_out = (const float*)d_in[24];
    float* out = (float*)d_out;

    k_dots<<<512, 256>>>(memory, u);
    k_softp<<<1, 512>>>();
    k_wmem<<<128, 128>>>(memory);
    k_G_gi<<<512, 192>>>(u, W_ff, b_ff, gWih_f, gbih_f, gWih_b, gbih_b);
    k_gru<<<2, 384>>>(gWhh_f, gbhh_f, gWhh_b, gbhh_b);
    k_uplus<<<256, 256>>>(u);
    k_gemm_nt<<<dim3(8, 8), 256>>>(0, W_k, 512, 128, b_k, nullptr, embed);
    k_gemm_nt<<<dim3(16, 8), 256>>>(1, lWih_f, 1024, 512, lbih_f, lbhh_f, nullptr);
    k_gemm_nt<<<dim3(16, 8), 256>>>(2, lWih_b, 1024, 512, lbih_b, lbhh_b, nullptr);
    k_lstm<<<16, 512>>>(lWhh_f, lWhh_b);
    k_out<<<512, 128>>>(W_out, b_out, out);
}

// round 8
// speedup vs baseline: 1.0032x; 1.0032x over previous
#include <cuda_runtime.h>
#include <cstdint>

// M=512 memories, T=512, D=128, E=512, NTAGS=74, GH=64, LH=256

__device__ __align__(16) float d_dots[512];
__device__ __align__(16) float d_p[512];
__device__ __align__(16) float d_wmem[512 * 128];
__device__ __align__(16) float d_gigru0[512 * 192];
__device__ __align__(16) float d_gigru1[512 * 192];
__device__ __align__(16) float d_hgru[512 * 128];
__device__ __align__(16) float d_s[512 * 128];
__device__ __align__(16) float d_x[512 * 512];
__device__ __align__(16) float d_gil0[512 * 1024];
__device__ __align__(16) float d_gil1[512 * 1024];
__device__ __align__(16) float d_hlstm[512 * 512];

__device__ __forceinline__ float sigf(float x) {
    return __fdividef(1.f, 1.f + __expf(-x));
}

// K1: dots[m] = <memory[m], u>
__global__ __launch_bounds__(256) void k_dots(const float* __restrict__ memory,
                                              const float* __restrict__ u) {
    const int tid = threadIdx.x;
    const float4* m4 = (const float4*)memory + (size_t)blockIdx.x * 16384;
    const float4* u4 = (const float4*)u;
    float acc = 0.f;
#pragma unroll 4
    for (int i = tid; i < 16384; i += 256) {
        float4 a = m4[i];
        float4 b = u4[i];
        acc += a.x * b.x + a.y * b.y + a.z * b.z + a.w * b.w;
    }
#pragma unroll
    for (int o = 16; o; o >>= 1) acc += __shfl_xor_sync(0xffffffffu, acc, o);
    __shared__ float sred[8];
    if ((tid & 31) == 0) sred[tid >> 5] = acc;
    __syncthreads();
    if (tid == 0) {
        float s = 0.f;
#pragma unroll
        for (int i = 0; i < 8; i++) s += sred[i];
        d_dots[blockIdx.x] = s;
    }
}

// K2: p = softmax(dots)
__global__ void k_softp() {
    const int tid = threadIdx.x;
    float v = d_dots[tid];
    __shared__ float s1[16];
    __shared__ float stot;
    float m = v;
#pragma unroll
    for (int o = 16; o; o >>= 1) m = fmaxf(m, __shfl_xor_sync(0xffffffffu, m, o));
    if ((tid & 31) == 0) s1[tid >> 5] = m;
    __syncthreads();
    if (tid == 0) {
        float mm = s1[0];
#pragma unroll
        for (int i = 1; i < 16; i++) mm = fmaxf(mm, s1[i]);
        stot = mm;
    }
    __syncthreads();
    float e = __expf(v - stot);
    float ssum = e;
#pragma unroll
    for (int o = 16; o; o >>= 1) ssum += __shfl_xor_sync(0xffffffffu, ssum, o);
    if ((tid & 31) == 0) s1[tid >> 5] = ssum;
    __syncthreads();
    if (tid == 0) {
        float ss = 0.f;
#pragma unroll
        for (int i = 0; i < 16; i++) ss += s1[i];
        stot = ss;
    }
    __syncthreads();
    d_p[tid] = e * __fdividef(1.f, stot);
}

// K3: wmem = sum_m p[m]*memory[m]
__global__ __launch_bounds__(128) void k_wmem(const float* __restrict__ memory) {
    __shared__ float ps[512];
    const int tid = threadIdx.x;
    for (int i = tid; i < 512; i += 128) ps[i] = d_p[i];
    __syncthreads();
    const float4* m4 = (const float4*)memory;
    const size_t base = (size_t)blockIdx.x * 128 + tid;
    float4 acc = {0.f, 0.f, 0.f, 0.f};
    for (int m = 0; m < 512; m += 8) {
#pragma unroll
        for (int q = 0; q < 8; q++) {
            float pm = ps[m + q];
            float4 v = m4[(size_t)(m + q) * 16384 + base];
            acc.x = fmaf(pm, v.x, acc.x);
            acc.y = fmaf(pm, v.y, acc.y);
            acc.z = fmaf(pm, v.z, acc.z);
            acc.w = fmaf(pm, v.w, acc.w);
        }
    }
    ((float4*)d_wmem)[base] = acc;
}

// K4: G[t] = [wmem[t]|u[t]]@W_ff.T + b_ff; gi_gru = G@gWih.T + gbih
__global__ __launch_bounds__(192) void k_G_gi(const float* __restrict__ u,
                                              const float* __restrict__ W_ff,
                                              const float* __restrict__ b_ff,
                                              const float* __restrict__ gWih_f,
                                              const float* __restrict__ gbih_f,
                                              const float* __restrict__ gWih_b,
                                              const float* __restrict__ gbih_b) {
    const int t = blockIdx.x;
    const int tid = threadIdx.x;
    __shared__ __align__(16) float c[256];
    __shared__ __align__(16) float gsm[128];
    if (tid < 128) {
        c[tid] = d_wmem[t * 128 + tid];
        c[128 + tid] = u[t * 128 + tid];
    }
    __syncthreads();
    if (tid < 128) {
        const float4* wr = (const float4*)(W_ff + tid * 256);
        const float4* c4 = (const float4*)c;
        float a0 = 0.f, a1 = 0.f;
#pragma unroll 8
        for (int i = 0; i < 64; i += 2) {
            float4 w0 = wr[i], w1 = wr[i + 1];
            float4 x0 = c4[i], x1 = c4[i + 1];
            a0 += w0.x * x0.x + w0.y * x0.y + w0.z * x0.z + w0.w * x0.w;
            a1 += w1.x * x1.x + w1.y * x1.y + w1.z * x1.z + w1.w * x1.w;
        }
        gsm[tid] = a0 + a1 + b_ff[tid];
    }
    __syncthreads();
    {
        const float4* wf = (const float4*)(gWih_f + tid * 128);
        const float4* wb = (const float4*)(gWih_b + tid * 128);
        const float4* g4 = (const float4*)gsm;
        float af = gbih_f[tid];
        float ab = gbih_b[tid];
#pragma unroll 8
        for (int i = 0; i < 32; i++) {
            float4 gv = g4[i];
            float4 a = wf[i];
            float4 b = wb[i];
            af += a.x * gv.x + a.y * gv.y + a.z * gv.z + a.w * gv.w;
            ab += b.x * gv.x + b.y * gv.y + b.z * gv.z + b.w * gv.w;
        }
        d_gigru0[t * 192 + tid] = af;
        d_gigru1[t * 192 + tid] = ab;
    }
}

// K5: BiGRU, one CTA per direction. Whh rows in regs (2 threads/row).
__global__ __launch_bounds__(384) void k_gru(const float* __restrict__ Whh_f,
                                             const float* __restrict__ bhh_f,
                                             const float* __restrict__ Whh_b,
                                             const float* __restrict__ bhh_b) {
    const int dir = blockIdx.x;
    const float* Whh = dir ? Whh_b : Whh_f;
    const float* bhh = dir ? bhh_b : bhh_f;
    const float* gi = dir ? d_gigru1 : d_gigru0;
    const int tid = threadIdx.x;
    const int r = tid >> 1;
    const int half = tid & 1;
    float4 w4[8];
    const float4* wsrc = (const float4*)(Whh + r * 64 + half * 32);
#pragma unroll
    for (int i = 0; i < 8; i++) w4[i] = wsrc[i];
    const float brow = bhh[r];
    __shared__ __align__(16) float hb[64];
    __shared__ float garr[192];
    __shared__ float gism[192];
    if (tid < 64) hb[tid] = 0.f;
    float hreg = 0.f;
    __syncthreads();
    for (int s = 0; s < 512; s++) {
        const int t = dir ? 511 - s : s;
        float gval = 0.f;
        if (!half) gval = gi[t * 192 + r];
        const float4* h4 = (const float4*)(hb + half * 32);
        float a0 = 0.f, a1 = 0.f, a2 = 0.f, a3 = 0.f;
#pragma unroll
        for (int i = 0; i < 8; i++) {
            float4 hv = h4[i];
            float4 wv = w4[i];
            a0 = fmaf(wv.x, hv.x, a0);
            a1 = fmaf(wv.y, hv.y, a1);
            a2 = fmaf(wv.z, hv.z, a2);
            a3 = fmaf(wv.w, hv.w, a3);
        }
        float acc = (a0 + a1) + (a2 + a3);
        acc += __shfl_xor_sync(0xffffffffu, acc, 1);
        if (!half) {
            garr[r] = acc + brow;
            gism[r] = gval;
        }
        __syncthreads();
        if (tid < 64) {
            float rr = sigf(gism[tid] + garr[tid]);
            float zz = sigf(gism[64 + tid] + garr[64 + tid]);
            float nn = tanhf(gism[128 + tid] + rr * garr[128 + tid]);
            hreg = (1.f - zz) * nn + zz * hreg;
            d_hgru[t * 128 + dir * 64 + tid] = hreg;
            hb[tid] = hreg;
        }
        __syncthreads();
    }
}

// K6: s = u + h_gru
__global__ void k_uplus(const float* __restrict__ u) {
    int i = blockIdx.x * blockDim.x + threadIdx.x;
    d_s[i] = u[i] + d_hgru[i];
}

// K7: generic NT GEMM C = A@B.T (+bias1+bias2+addm), M=512, 64x64 tiles
__global__ __launch_bounds__(256) void k_gemm_nt(int mode, const float* __restrict__ B,
                                                 int N, int K,
                                                 const float* __restrict__ bias1,
                                                 const float* __restrict__ bias2,
                                                 const float* __restrict__ addm) {
    const float* A = (mode == 0) ? d_s : d_x;
    float* C = (mode == 0) ? d_x : (mode == 1 ? d_gil0 : d_gil1);
    __shared__ __align__(16) float As[16][64];
    __shared__ __align__(16) float Bs[16][64];
    const int tid = threadIdx.x;
    const int tx = tid & 15, ty = tid >> 4;
    const int lrow = tid >> 2, kq = (tid & 3) * 4;
    const float* Ab = A + (size_t)(blockIdx.y * 64 + lrow) * K + kq;
    const float* Bb = B + (size_t)(blockIdx.x * 64 + lrow) * K + kq;
    float acc[4][4] = {};
    for (int k0 = 0; k0 < K; k0 += 16) {
        float4 av = *(const float4*)(Ab + k0);
        float4 bv = *(const float4*)(Bb + k0);
        __syncthreads();
        As[kq][lrow] = av.x;
        As[kq + 1][lrow] = av.y;
        As[kq + 2][lrow] = av.z;
        As[kq + 3][lrow] = av.w;
        Bs[kq][lrow] = bv.x;
        Bs[kq + 1][lrow] = bv.y;
        Bs[kq + 2][lrow] = bv.z;
        Bs[kq + 3][lrow] = bv.w;
        __syncthreads();
#pragma unroll
        for (int kk = 0; kk < 16; kk++) {
            float4 a4 = *(const float4*)(&As[kk][ty * 4]);
            float4 b4 = *(const float4*)(&Bs[kk][tx * 4]);
            float ar[4] = {a4.x, a4.y, a4.z, a4.w};
            float br[4] = {b4.x, b4.y, b4.z, b4.w};
#pragma unroll
            for (int i = 0; i < 4; i++)
#pragma unroll
                for (int j = 0; j < 4; j++)
                    acc[i][j] = fmaf(ar[i], br[j], acc[i][j]);
        }
    }
#pragma unroll
    for (int i = 0; i < 4; i++) {
        int m = blockIdx.y * 64 + ty * 4 + i;
#pragma unroll
        for (int j = 0; j < 4; j++) {
            int n = blockIdx.x * 64 + tx * 4 + j;
            float v = acc[i][j];
            if (bias1) v += bias1[n];
            if (bias2) v += bias2[n];
            if (addm) v += addm[(size_t)m * N + n];
            C[(size_t)m * N + n] = v;
        }
    }
}

// K8: BiLSTM, cluster of 8 CTAs per direction. Whh register-resident.
__global__ __cluster_dims__(8, 1, 1) __launch_bounds__(512, 1)
void k_lstm(const float* __restrict__ Whh_f, const float* __restrict__ Whh_b) {
    const int dir = blockIdx.x >> 3;
    const int rank = blockIdx.x & 7;
    const float* Whh = dir ? Whh_b : Whh_f;
    const float* gi = dir ? d_gil1 : d_gil0;
    const int tid = threadIdx.x;
    const int lrow = tid >> 2;   // 0..127 local gate row
    const int q = tid & 3;       // quarter of the 256-dot
    const int gate = lrow >> 5;
    const int unit = lrow & 31;
    const int grow = gate * 256 + rank * 32 + unit;
    float4 w4[16];
    const float4* wsrc = (const float4*)(Whh + grow * 256 + q * 64);
#pragma unroll
    for (int i = 0; i < 16; i++) w4[i] = wsrc[i];
    __shared__ __align__(16) float hbuf[2][256];
    __shared__ float garr[128];
    if (tid < 256) hbuf[0][tid] = 0.f;
    float cst = 0.f;
    asm volatile("barrier.cluster.arrive.aligned;\n\tbarrier.cluster.wait.aligned;" ::: "memory");
    for (int s = 0; s < 512; s++) {
        const int t = dir ? 511 - s : s;
        float gval = (q == 0) ? gi[t * 1024 + grow] : 0.f;  // incl. bih+bhh
        const float4* h4 = (const float4*)(&hbuf[s & 1][q * 64]);
        float a0 = 0.f, a1 = 0.f, a2 = 0.f, a3 = 0.f;
#pragma unroll
        for (int i = 0; i < 16; i++) {
            float4 hv = h4[i];
            float4 wv = w4[i];
            a0 = fmaf(wv.x, hv.x, a0);
            a1 = fmaf(wv.y, hv.y, a1);
            a2 = fmaf(wv.z, hv.z, a2);
            a3 = fmaf(wv.w, hv.w, a3);
        }
        float acc = (a0 + a1) + (a2 + a3);
        acc += __shfl_xor_sync(0xffffffffu, acc, 1);
        acc += __shfl_xor_sync(0xffffffffu, acc, 2);
        if (q == 0) garr[lrow] = acc + gval;
        __syncthreads();
        if (tid < 32) {
            float iv = sigf(garr[tid]);
            float fv = sigf(garr[32 + tid]);
            float gv = tanhf(garr[64 + tid]);
            float ov = sigf(garr[96 + tid]);
            cst = fv * cst + iv * gv;
            float hv = ov * tanhf(cst);
            d_hlstm[t * 512 + dir * 256 + rank * 32 + tid] = hv;
            unsigned laddr =
                (unsigned)__cvta_generic_to_shared(&hbuf[(s & 1) ^ 1][rank * 32 + tid]);
#pragma unroll
            for (int rt = 0; rt < 8; rt++) {
                unsigned ra;
                asm volatile("mapa.shared::cluster.u32 %0, %1, %2;"
                             : "=r"(ra)
                             : "r"(laddr), "r"(rt));
                asm volatile("st.shared::cluster.f32 [%0], %1;" ::"r"(ra), "f"(hv)
                             : "memory");
            }
        }
        asm volatile("barrier.cluster.arrive.aligned;\n\tbarrier.cluster.wait.aligned;" ::: "memory");
    }
}

// K9: logits + row softmax -> out [512,74]
__global__ __launch_bounds__(128) void k_out(const float* __restrict__ W_out,
                                             const float* __restrict__ b_out,
                                             float* __restrict__ out) {
    const int t = blockIdx.x;
    const int tid = threadIdx.x;
    __shared__ __align__(16) float cb[512];
    __shared__ float red[128];
    ((float4*)cb)[tid] = ((const float4*)(d_hlstm + (size_t)t * 512))[tid];
    __syncthreads();
    float lg = -1e30f;
    if (tid < 74) {
        const float4* wr = (const float4*)(W_out + tid * 512);
        const float4* c4 = (const float4*)cb;
        float a0 = 0.f, a1 = 0.f, a2 = 0.f, a3 = 0.f;
#pragma unroll 8
        for (int i = 0; i < 128; i += 4) {
            float4 w0 = wr[i], w1 = wr[i + 1], w2 = wr[i + 2], w3 = wr[i + 3];
            float4 x0 = c4[i], x1 = c4[i + 1], x2 = c4[i + 2], x3 = c4[i + 3];
            a0 += w0.x * x0.x + w0.y * x0.y + w0.z * x0.z + w0.w * x0.w;
            a1 += w1.x * x1.x + w1.y * x1.y + w1.z * x1.z + w1.w * x1.w;
            a2 += w2.x * x2.x + w2.y * x2.y + w2.z * x2.z + w2.w * x2.w;
            a3 += w3.x * x3.x + w3.y * x3.y + w3.z * x3.z + w3.w * x3.w;
        }
        lg = (a0 + a1) + (a2 + a3) + b_out[tid];
    }
    red[tid] = lg;
    __syncthreads();
#pragma unroll
    for (int o = 64; o > 0; o >>= 1) {
        if (tid < o) red[tid] = fmaxf(red[tid], red[tid + o]);
        __syncthreads();
    }
    float mx = red[0];
    __syncthreads();
    float e = (tid < 74) ? __expf(lg - mx) : 0.f;
    red[tid] = e;
    __syncthreads();
#pragma unroll
    for (int o = 64; o > 0; o >>= 1) {
        if (tid < o) red[tid] += red[tid + o];
        __syncthreads();
    }
    float inv = __fdividef(1.f, red[0]);
    if (tid < 74) out[t * 74 + tid] = e * inv;
}

extern "C" void kernel_launch(void* const* d_in, const int* in_sizes, int n_in,
                              void* d_out, int out_size) {
    const float* memory = (const float*)d_in[0];
    const float* u = (const float*)d_in[1];
    const float* embed = (const float*)d_in[2];
    const float* W_ff = (const float*)d_in[3];
    const float* b_ff = (const float*)d_in[4];
    const float* gWih_f = (const float*)d_in[5];
    const float* gWhh_f = (const float*)d_in[6];
    const float* gbih_f = (const float*)d_in[7];
    const float* gbhh_f = (const float*)d_in[8];
    const float* gWih_b = (const float*)d_in[9];
    const float* gWhh_b = (const float*)d_in[10];
    const float* gbih_b = (const float*)d_in[11];
    const float* gbhh_b = (const float*)d_in[12];
    const float* W_k = (const float*)d_in[13];
    const float* b_k = (const float*)d_in[14];
    const float* lWih_f = (const float*)d_in[15];
    const float* lWhh_f = (const float*)d_in[16];
    const float* lbih_f = (const float*)d_in[17];
    const float* lbhh_f = (const float*)d_in[18];
    const float* lWih_b = (const float*)d_in[19];
    const float* lWhh_b = (const float*)d_in[20];
    const float* lbih_b = (const float*)d_in[21];
    const float* lbhh_b = (const float*)d_in[22];
    const float* W_out = (const float*)d_in[23];
    const float* b_out = (const float*)d_in[24];
    float* out = (float*)d_out;

    k_dots<<<512, 256>>>(memory, u);
    k_softp<<<1, 512>>>();
    k_wmem<<<128, 128>>>(memory);
    k_G_gi<<<512, 192>>>(u, W_ff, b_ff, gWih_f, gbih_f, gWih_b, gbih_b);
    k_gru<<<2, 384>>>(gWhh_f, gbhh_f, gWhh_b, gbhh_b);
    k_uplus<<<256, 256>>>(u);
    k_gemm_nt<<<dim3(8, 8), 256>>>(0, W_k, 512, 128, b_k, nullptr, embed);
    k_gemm_nt<<<dim3(16, 8), 256>>>(1, lWih_f, 1024, 512, lbih_f, lbhh_f, nullptr);
    k_gemm_nt<<<dim3(16, 8), 256>>>(2, lWih_b, 1024, 512, lbih_b, lbhh_b, nullptr);
    k_lstm<<<16, 512>>>(lWhh_f, lWhh_b);
    k_out<<<512, 128>>>(W_out, b_out, out);
}

// round 9
// speedup vs baseline: 1.0033x; 1.0000x over previous
#include <cuda_runtime.h>
#include <cstdint>

// M=512 memories, T=512, D=128, E=512, NTAGS=74, GH=64, LH=256

__device__ __align__(16) float d_dots[512];
__device__ __align__(16) float d_p[512];
__device__ __align__(16) float d_wmem[512 * 128];
__device__ __align__(16) float d_gigru0[512 * 192];
__device__ __align__(16) float d_gigru1[512 * 192];
__device__ __align__(16) float d_hgru[512 * 128];
__device__ __align__(16) float d_s[512 * 128];
__device__ __align__(16) float d_x[512 * 512];
__device__ __align__(16) float d_gil0[512 * 1024];
__device__ __align__(16) float d_gil1[512 * 1024];
__device__ __align__(16) float d_hlstm[512 * 512];

__device__ __forceinline__ float sigf(float x) {
    return __fdividef(1.f, 1.f + __expf(-x));
}

// K1: dots[m] = <memory[m], u>
__global__ __launch_bounds__(256) void k_dots(const float* __restrict__ memory,
                                              const float* __restrict__ u) {
    const int tid = threadIdx.x;
    const float4* m4 = (const float4*)memory + (size_t)blockIdx.x * 16384;
    const float4* u4 = (const float4*)u;
    float acc = 0.f;
#pragma unroll 4
    for (int i = tid; i < 16384; i += 256) {
        float4 a = m4[i];
        float4 b = u4[i];
        acc += a.x * b.x + a.y * b.y + a.z * b.z + a.w * b.w;
    }
#pragma unroll
    for (int o = 16; o; o >>= 1) acc += __shfl_xor_sync(0xffffffffu, acc, o);
    __shared__ float sred[8];
    if ((tid & 31) == 0) sred[tid >> 5] = acc;
    __syncthreads();
    if (tid == 0) {
        float s = 0.f;
#pragma unroll
        for (int i = 0; i < 8; i++) s += sred[i];
        d_dots[blockIdx.x] = s;
    }
}

// K2: p = softmax(dots)
__global__ void k_softp() {
    const int tid = threadIdx.x;
    float v = d_dots[tid];
    __shared__ float s1[16];
    __shared__ float stot;
    float m = v;
#pragma unroll
    for (int o = 16; o; o >>= 1) m = fmaxf(m, __shfl_xor_sync(0xffffffffu, m, o));
    if ((tid & 31) == 0) s1[tid >> 5] = m;
    __syncthreads();
    if (tid == 0) {
        float mm = s1[0];
#pragma unroll
        for (int i = 1; i < 16; i++) mm = fmaxf(mm, s1[i]);
        stot = mm;
    }
    __syncthreads();
    float e = __expf(v - stot);
    float ssum = e;
#pragma unroll
    for (int o = 16; o; o >>= 1) ssum += __shfl_xor_sync(0xffffffffu, ssum, o);
    if ((tid & 31) == 0) s1[tid >> 5] = ssum;
    __syncthreads();
    if (tid == 0) {
        float ss = 0.f;
#pragma unroll
        for (int i = 0; i < 16; i++) ss += s1[i];
        stot = ss;
    }
    __syncthreads();
    d_p[tid] = e * __fdividef(1.f, stot);
}

// K3: wmem = sum_m p[m]*memory[m]
__global__ __launch_bounds__(128) void k_wmem(const float* __restrict__ memory) {
    __shared__ float ps[512];
    const int tid = threadIdx.x;
    for (int i = tid; i < 512; i += 128) ps[i] = d_p[i];
    __syncthreads();
    const float4* m4 = (const float4*)memory;
    const size_t base = (size_t)blockIdx.x * 128 + tid;
    float4 acc = {0.f, 0.f, 0.f, 0.f};
    for (int m = 0; m < 512; m += 8) {
#pragma unroll
        for (int q = 0; q < 8; q++) {
            float pm = ps[m + q];
            float4 v = m4[(size_t)(m + q) * 16384 + base];
            acc.x = fmaf(pm, v.x, acc.x);
            acc.y = fmaf(pm, v.y, acc.y);
            acc.z = fmaf(pm, v.z, acc.z);
            acc.w = fmaf(pm, v.w, acc.w);
        }
    }
    ((float4*)d_wmem)[base] = acc;
}

// K4: G[t] = [wmem[t]|u[t]]@W_ff.T + b_ff; gi_gru = G@gWih.T + gbih
__global__ __launch_bounds__(192) void k_G_gi(const float* __restrict__ u,
                                              const float* __restrict__ W_ff,
                                              const float* __restrict__ b_ff,
                                              const float* __restrict__ gWih_f,
                                              const float* __restrict__ gbih_f,
                                              const float* __restrict__ gWih_b,
                                              const float* __restrict__ gbih_b) {
    const int t = blockIdx.x;
    const int tid = threadIdx.x;
    __shared__ __align__(16) float c[256];
    __shared__ __align__(16) float gsm[128];
    if (tid < 128) {
        c[tid] = d_wmem[t * 128 + tid];
        c[128 + tid] = u[t * 128 + tid];
    }
    __syncthreads();
    if (tid < 128) {
        const float4* wr = (const float4*)(W_ff + tid * 256);
        const float4* c4 = (const float4*)c;
        float a0 = 0.f, a1 = 0.f;
#pragma unroll 8
        for (int i = 0; i < 64; i += 2) {
            float4 w0 = wr[i], w1 = wr[i + 1];
            float4 x0 = c4[i], x1 = c4[i + 1];
            a0 += w0.x * x0.x + w0.y * x0.y + w0.z * x0.z + w0.w * x0.w;
            a1 += w1.x * x1.x + w1.y * x1.y + w1.z * x1.z + w1.w * x1.w;
        }
        gsm[tid] = a0 + a1 + b_ff[tid];
    }
    __syncthreads();
    {
        const float4* wf = (const float4*)(gWih_f + tid * 128);
        const float4* wb = (const float4*)(gWih_b + tid * 128);
        const float4* g4 = (const float4*)gsm;
        float af = gbih_f[tid];
        float ab = gbih_b[tid];
#pragma unroll 8
        for (int i = 0; i < 32; i++) {
            float4 gv = g4[i];
            float4 a = wf[i];
            float4 b = wb[i];
            af += a.x * gv.x + a.y * gv.y + a.z * gv.z + a.w * gv.w;
            ab += b.x * gv.x + b.y * gv.y + b.z * gv.z + b.w * gv.w;
        }
        d_gigru0[t * 192 + tid] = af;
        d_gigru1[t * 192 + tid] = ab;
    }
}

// K5: BiGRU, one CTA per direction. Whh rows in regs (2 threads/row).
__global__ __launch_bounds__(384) void k_gru(const float* __restrict__ Whh_f,
                                             const float* __restrict__ bhh_f,
                                             const float* __restrict__ Whh_b,
                                             const float* __restrict__ bhh_b) {
    const int dir = blockIdx.x;
    const float* Whh = dir ? Whh_b : Whh_f;
    const float* bhh = dir ? bhh_b : bhh_f;
    const float* gi = dir ? d_gigru1 : d_gigru0;
    const int tid = threadIdx.x;
    const int r = tid >> 1;
    const int half = tid & 1;
    float4 w4[8];
    const float4* wsrc = (const float4*)(Whh + r * 64 + half * 32);
#pragma unroll
    for (int i = 0; i < 8; i++) w4[i] = wsrc[i];
    const float brow = bhh[r];
    __shared__ __align__(16) float hb[64];
    __shared__ float garr[192];
    __shared__ float gism[192];
    if (tid < 64) hb[tid] = 0.f;
    float hreg = 0.f;
    __syncthreads();
    for (int s = 0; s < 512; s++) {
        const int t = dir ? 511 - s : s;
        float gval = 0.f;
        if (!half) gval = gi[t * 192 + r];
        const float4* h4 = (const float4*)(hb + half * 32);
        float a0 = 0.f, a1 = 0.f, a2 = 0.f, a3 = 0.f;
#pragma unroll
        for (int i = 0; i < 8; i++) {
            float4 hv = h4[i];
            float4 wv = w4[i];
            a0 = fmaf(wv.x, hv.x, a0);
            a1 = fmaf(wv.y, hv.y, a1);
            a2 = fmaf(wv.z, hv.z, a2);
            a3 = fmaf(wv.w, hv.w, a3);
        }
        float acc = (a0 + a1) + (a2 + a3);
        acc += __shfl_xor_sync(0xffffffffu, acc, 1);
        if (!half) {
            garr[r] = acc + brow;
            gism[r] = gval;
        }
        __syncthreads();
        if (tid < 64) {
            float rr = sigf(gism[tid] + garr[tid]);
            float zz = sigf(gism[64 + tid] + garr[64 + tid]);
            float nn = tanhf(gism[128 + tid] + rr * garr[128 + tid]);
            hreg = (1.f - zz) * nn + zz * hreg;
            d_hgru[t * 128 + dir * 64 + tid] = hreg;
            hb[tid] = hreg;
        }
        __syncthreads();
    }
}

// K6: s = u + h_gru
__global__ void k_uplus(const float* __restrict__ u) {
    int i = blockIdx.x * blockDim.x + threadIdx.x;
    d_s[i] = u[i] + d_hgru[i];
}

// K7: generic NT GEMM C = A@B.T (+bias1+bias2+addm), M=512, 64x64 tiles
__global__ __launch_bounds__(256) void k_gemm_nt(int mode, const float* __restrict__ B,
                                                 int N, int K,
                                                 const float* __restrict__ bias1,
                                                 const float* __restrict__ bias2,
                                                 const float* __restrict__ addm) {
    const float* A = (mode == 0) ? d_s : d_x;
    float* C = (mode == 0) ? d_x : (mode == 1 ? d_gil0 : d_gil1);
    __shared__ __align__(16) float As[16][64];
    __shared__ __align__(16) float Bs[16][64];
    const int tid = threadIdx.x;
    const int tx = tid & 15, ty = tid >> 4;
    const int lrow = tid >> 2, kq = (tid & 3) * 4;
    const float* Ab = A + (size_t)(blockIdx.y * 64 + lrow) * K + kq;
    const float* Bb = B + (size_t)(blockIdx.x * 64 + lrow) * K + kq;
    float acc[4][4] = {};
    for (int k0 = 0; k0 < K; k0 += 16) {
        float4 av = *(const float4*)(Ab + k0);
        float4 bv = *(const float4*)(Bb + k0);
        __syncthreads();
        As[kq][lrow] = av.x;
        As[kq + 1][lrow] = av.y;
        As[kq + 2][lrow] = av.z;
        As[kq + 3][lrow] = av.w;
        Bs[kq][lrow] = bv.x;
        Bs[kq + 1][lrow] = bv.y;
        Bs[kq + 2][lrow] = bv.z;
        Bs[kq + 3][lrow] = bv.w;
        __syncthreads();
#pragma unroll
        for (int kk = 0; kk < 16; kk++) {
            float4 a4 = *(const float4*)(&As[kk][ty * 4]);
            float4 b4 = *(const float4*)(&Bs[kk][tx * 4]);
            float ar[4] = {a4.x, a4.y, a4.z, a4.w};
            float br[4] = {b4.x, b4.y, b4.z, b4.w};
#pragma unroll
            for (int i = 0; i < 4; i++)
#pragma unroll
                for (int j = 0; j < 4; j++)
                    acc[i][j] = fmaf(ar[i], br[j], acc[i][j]);
        }
    }
#pragma unroll
    for (int i = 0; i < 4; i++) {
        int m = blockIdx.y * 64 + ty * 4 + i;
#pragma unroll
        for (int j = 0; j < 4; j++) {
            int n = blockIdx.x * 64 + tx * 4 + j;
            float v = acc[i][j];
            if (bias1) v += bias1[n];
            if (bias2) v += bias2[n];
            if (addm) v += addm[(size_t)m * N + n];
            C[(size_t)m * N + n] = v;
        }
    }
}

// K8: BiLSTM, cluster of 8 CTAs per direction. Whh register-resident.
__global__ __cluster_dims__(8, 1, 1) __launch_bounds__(512, 1)
void k_lstm(const float* __restrict__ Whh_f, const float* __restrict__ Whh_b) {
    const int dir = blockIdx.x >> 3;
    const int rank = blockIdx.x & 7;
    const float* Whh = dir ? Whh_b : Whh_f;
    const float* gi = dir ? d_gil1 : d_gil0;
    const int tid = threadIdx.x;
    const int lrow = tid >> 2;   // 0..127 local gate row
    const int q = tid & 3;       // quarter of the 256-dot
    const int gate = lrow >> 5;
    const int unit = lrow & 31;
    const int grow = gate * 256 + rank * 32 + unit;
    float4 w4[16];
    const float4* wsrc = (const float4*)(Whh + grow * 256 + q * 64);
#pragma unroll
    for (int i = 0; i < 16; i++) w4[i] = wsrc[i];
    __shared__ __align__(16) float hbuf[2][256];
    __shared__ float garr[128];
    if (tid < 256) hbuf[0][tid] = 0.f;
    float cst = 0.f;
    asm volatile("barrier.cluster.arrive.aligned;\n\tbarrier.cluster.wait.aligned;" ::: "memory");
    for (int s = 0; s < 512; s++) {
        const int t = dir ? 511 - s : s;
        float gval = (q == 0) ? gi[t * 1024 + grow] : 0.f;  // incl. bih+bhh
        const float4* h4 = (const float4*)(&hbuf[s & 1][q * 64]);
        float a0 = 0.f, a1 = 0.f, a2 = 0.f, a3 = 0.f;
#pragma unroll
        for (int i = 0; i < 16; i++) {
            float4 hv = h4[i];
            float4 wv = w4[i];
            a0 = fmaf(wv.x, hv.x, a0);
            a1 = fmaf(wv.y, hv.y, a1);
            a2 = fmaf(wv.z, hv.z, a2);
            a3 = fmaf(wv.w, hv.w, a3);
        }
        float acc = (a0 + a1) + (a2 + a3);
        acc += __shfl_xor_sync(0xffffffffu, acc, 1);
        acc += __shfl_xor_sync(0xffffffffu, acc, 2);
        if (q == 0) garr[lrow] = acc + gval;
        __syncthreads();
        if (tid < 32) {
            float iv = sigf(garr[tid]);
            float fv = sigf(garr[32 + tid]);
            float gv = tanhf(garr[64 + tid]);
            float ov = sigf(garr[96 + tid]);
            cst = fv * cst + iv * gv;
            float hv = ov * tanhf(cst);
            d_hlstm[t * 512 + dir * 256 + rank * 32 + tid] = hv;
            unsigned laddr =
                (unsigned)__cvta_generic_to_shared(&hbuf[(s & 1) ^ 1][rank * 32 + tid]);
#pragma unroll
            for (int rt = 0; rt < 8; rt++) {
                unsigned ra;
                asm volatile("mapa.shared::cluster.u32 %0, %1, %2;"
                             : "=r"(ra)
                             : "r"(laddr), "r"(rt));
                asm volatile("st.shared::cluster.f32 [%0], %1;" ::"r"(ra), "f"(hv)
                             : "memory");
            }
        }
        asm volatile("barrier.cluster.arrive.aligned;\n\tbarrier.cluster.wait.aligned;" ::: "memory");
    }
}

// K9: logits + row softmax -> out [512,74]
__global__ __launch_bounds__(128) void k_out(const float* __restrict__ W_out,
                                             const float* __restrict__ b_out,
                                             float* __restrict__ out) {
    const int t = blockIdx.x;
    const int tid = threadIdx.x;
    __shared__ __align__(16) float cb[512];
    __shared__ float red[128];
    ((float4*)cb)[tid] = ((const float4*)(d_hlstm + (size_t)t * 512))[tid];
    __syncthreads();
    float lg = -1e30f;
    if (tid < 74) {
        const float4* wr = (const float4*)(W_out + tid * 512);
        const float4* c4 = (const float4*)cb;
        float a0 = 0.f, a1 = 0.f, a2 = 0.f, a3 = 0.f;
#pragma unroll 8
        for (int i = 0; i < 128; i += 4) {
            float4 w0 = wr[i], w1 = wr[i + 1], w2 = wr[i + 2], w3 = wr[i + 3];
            float4 x0 = c4[i], x1 = c4[i + 1], x2 = c4[i + 2], x3 = c4[i + 3];
            a0 += w0.x * x0.x + w0.y * x0.y + w0.z * x0.z + w0.w * x0.w;
            a1 += w1.x * x1.x + w1.y * x1.y + w1.z * x1.z + w1.w * x1.w;
            a2 += w2.x * x2.x + w2.y * x2.y + w2.z * x2.z + w2.w * x2.w;
            a3 += w3.x * x3.x + w3.y * x3.y + w3.z * x3.z + w3.w * x3.w;
        }
        lg = (a0 + a1) + (a2 + a3) + b_out[tid];
    }
    red[tid] = lg;
    __syncthreads();
#pragma unroll
    for (int o = 64; o > 0; o >>= 1) {
        if (tid < o) red[tid] = fmaxf(red[tid], red[tid + o]);
        __syncthreads();
    }
    float mx = red[0];
    __syncthreads();
    float e = (tid < 74) ? __expf(lg - mx) : 0.f;
    red[tid] = e;
    __syncthreads();
#pragma unroll
    for (int o = 64; o > 0; o >>= 1) {
        if (tid < o) red[tid] += red[tid + o];
        __syncthreads();
    }
    float inv = __fdividef(1.f, red[0]);
    if (tid < 74) out[t * 74 + tid] = e * inv;
}

extern "C" void kernel_launch(void* const* d_in, const int* in_sizes, int n_in,
                              void* d_out, int out_size) {
    const float* memory = (const float*)d_in[0];
    const float* u = (const float*)d_in[1];
    const float* embed = (const float*)d_in[2];
    const float* W_ff = (const float*)d_in[3];
    const float* b_ff = (const float*)d_in[4];
    const float* gWih_f = (const float*)d_in[5];
    const float* gWhh_f = (const float*)d_in[6];
    const float* gbih_f = (const float*)d_in[7];
    const float* gbhh_f = (const float*)d_in[8];
    const float* gWih_b = (const float*)d_in[9];
    const float* gWhh_b = (const float*)d_in[10];
    const float* gbih_b = (const float*)d_in[11];
    const float* gbhh_b = (const float*)d_in[12];
    const float* W_k = (const float*)d_in[13];
    const float* b_k = (const float*)d_in[14];
    const float* lWih_f = (const float*)d_in[15];
    const float* lWhh_f = (const float*)d_in[16];
    const float* lbih_f = (const float*)d_in[17];
    const float* lbhh_f = (const float*)d_in[18];
    const float* lWih_b = (const float*)d_in[19];
    const float* lWhh_b = (const float*)d_in[20];
    const float* lbih_b = (const float*)d_in[21];
    const float* lbhh_b = (const float*)d_in[22];
    const float* W_out = (const float*)d_in[23];
    const float* b_out = (const float*)d_in[24];
    float* out = (float*)d_out;

    k_dots<<<512, 256>>>(memory, u);
    k_softp<<<1, 512>>>();
    k_wmem<<<128, 128>>>(memory);
    k_G_gi<<<512, 192>>>(u, W_ff, b_ff, gWih_f, gbih_f, gWih_b, gbih_b);
    k_gru<<<2, 384>>>(gWhh_f, gbhh_f, gWhh_b, gbhh_b);
    k_uplus<<<256, 256>>>(u);
    k_gemm_nt<<<dim3(8, 8), 256>>>(0, W_k, 512, 128, b_k, nullptr, embed);
    k_gemm_nt<<<dim3(16, 8), 256>>>(1, lWih_f, 1024, 512, lbih_f, lbhh_f, nullptr);
    k_gemm_nt<<<dim3(16, 8), 256>>>(2, lWih_b, 1024, 512, lbih_b, lbhh_b, nullptr);
    k_lstm<<<16, 512>>>(lWhh_f, lWhh_b);
    k_out<<<512, 128>>>(W_out, b_out, out);
}